// round 1
// baseline (speedup 1.0000x reference)
#include <cuda_runtime.h>
#include <cuda_bf16.h>
#include <cstdint>

// ============================================================================
// PNeRF coordinate extension as a chunked affine prefix scan.
//
// Math: atom i's placement relative to the previous frame is the rigid motion
//   rotation S_i (rows, world = local @ M):
//     S = [[ct, cp*st, sp*st], [-st, cp*ct, sp*ct], [0, -sp, cp]]
//   translation p_i = bl * S_i[0]   (in the previous frame's coords)
// State (M, t): x_world = x_local @ M + t.  Step: M' = S M ; t' = t + bl*M'[0]
// Chunk composite (P, q) acts on state: (M,t) -> (P M, q M + t).
// Combine earlier A then later B: (B.P A.P, B.q A.P + A.q)  -- associative.
// ============================================================================

#define C1   50      // atoms per chunk (per thread)
#define TPB  96      // chunks per block
#define MAXCHUNKS 60096
#define MAXBLK    704

struct Aff { float m[9]; float t[3]; };

__device__ float g_chunkScan[MAXCHUNKS * 12];   // inclusive within-block scans
__device__ float g_blockComp[MAXBLK * 12];      // per-block composites
__device__ float g_basePrefix[MAXBLK * 12];     // state at start of each block

// ---------------------------------------------------------------------------
// Accurate fp32 sincos (immune to --use_fast_math): Cody-Waite + Cephes polys.
// Valid for |x| <= ~4 (inputs are in [-pi, pi] and [1.9, 2.1]).
// ---------------------------------------------------------------------------
__device__ __forceinline__ void fsincos(float x, float& s, float& c) {
    float q = rintf(x * 0.6366197723675814f);          // 2/pi
    float r = fmaf(q, -1.5707963705062866f, x);        // x - q*PIO2_HI
    r = fmaf(q, 4.37113883e-8f, r);                    // - q*PIO2_LO (LO<0)
    int iq = (int)q;
    float z = r * r;
    // sin poly
    float ps = fmaf(z, -1.9515295891e-4f, 8.3321608736e-3f);
    ps = fmaf(z, ps, -1.6666654611e-1f);
    float sr = fmaf(r * z, ps, r);
    // cos poly
    float pc = fmaf(z, 2.443315711809948e-5f, -1.388731625493765e-3f);
    pc = fmaf(z, pc, 4.166664568298827e-2f);
    float cr = fmaf(z * z, pc, fmaf(z, -0.5f, 1.0f));
    bool sw = (iq & 1);
    float ss = sw ? cr : sr;
    float cc = sw ? sr : cr;
    if (iq & 2)        ss = -ss;
    if ((iq + 1) & 2)  cc = -cc;
    s = ss; c = cc;
}

// Combine: A earlier, B later (also used as apply(composite B, state A)).
__device__ __forceinline__ Aff cmb(const Aff& A, const Aff& B) {
    Aff r;
#pragma unroll
    for (int i = 0; i < 3; i++) {
        float b0 = B.m[3*i], b1 = B.m[3*i+1], b2 = B.m[3*i+2];
#pragma unroll
        for (int j = 0; j < 3; j++)
            r.m[3*i+j] = fmaf(b0, A.m[j], fmaf(b1, A.m[3+j], b2 * A.m[6+j]));
    }
#pragma unroll
    for (int j = 0; j < 3; j++)
        r.t[j] = fmaf(B.t[0], A.m[j], fmaf(B.t[1], A.m[3+j],
                 fmaf(B.t[2], A.m[6+j], A.t[j])));
    return r;
}

__device__ __forceinline__ void chain_step(float bl, float th, float ph, Aff& s) {
    float st, ct, sp, cp;
    fsincos(th, st, ct);
    fsincos(ph, sp, cp);
    float a = cp * st, b = sp * st, c = cp * ct, d = sp * ct;
#pragma unroll
    for (int j = 0; j < 3; j++) {
        float m0 = s.m[j], m1 = s.m[3+j], m2 = s.m[6+j];
        float r0 = fmaf(ct, m0, fmaf(a, m1, b * m2));
        float r1 = fmaf(c,  m1, fmaf(d, m2, -st * m0));
        float r2 = fmaf(cp, m2, -sp * m1);
        s.m[j] = r0; s.m[3+j] = r1; s.m[6+j] = r2;
        s.t[j] = fmaf(bl, r0, s.t[j]);
    }
}

// Re-orthonormalize a frame (mirrors reference's per-step renormalization,
// applied at chunk granularity). rows: r0=bc, r1=n x bc, r2=n  =>  r1 = r2 x r0
__device__ __forceinline__ void reortho(Aff& s) {
    float inv = rsqrtf(fmaf(s.m[0], s.m[0], fmaf(s.m[1], s.m[1], s.m[2]*s.m[2])));
    s.m[0] *= inv; s.m[1] *= inv; s.m[2] *= inv;
    float d = fmaf(s.m[6], s.m[0], fmaf(s.m[7], s.m[1], s.m[8]*s.m[2]));
    s.m[6] = fmaf(-d, s.m[0], s.m[6]);
    s.m[7] = fmaf(-d, s.m[1], s.m[7]);
    s.m[8] = fmaf(-d, s.m[2], s.m[8]);
    inv = rsqrtf(fmaf(s.m[6], s.m[6], fmaf(s.m[7], s.m[7], s.m[8]*s.m[8])));
    s.m[6] *= inv; s.m[7] *= inv; s.m[8] *= inv;
    s.m[3] = s.m[7]*s.m[2] - s.m[8]*s.m[1];
    s.m[4] = s.m[8]*s.m[0] - s.m[6]*s.m[2];
    s.m[5] = s.m[6]*s.m[1] - s.m[7]*s.m[0];
}

__device__ __forceinline__ void aff_store(float* p, const Aff& a) {
#pragma unroll
    for (int i = 0; i < 9; i++) p[i] = a.m[i];
#pragma unroll
    for (int i = 0; i < 3; i++) p[9+i] = a.t[i];
}
__device__ __forceinline__ Aff aff_load(const float* p) {
    Aff a;
#pragma unroll
    for (int i = 0; i < 9; i++) a.m[i] = p[i];
#pragma unroll
    for (int i = 0; i < 3; i++) a.t[i] = p[9+i];
    return a;
}

// ---------------------------------------------------------------------------
// K1: per-chunk composites + in-block inclusive scan + block composite.
// ---------------------------------------------------------------------------
__global__ void __launch_bounds__(TPB) k1_chunks(const float* __restrict__ inner, int n) {
    __shared__ float sh[TPB * 12];
    int j = threadIdx.x, b = blockIdx.x;
    int chunk = b * TPB + j;
    int base = chunk * C1;

    Aff s = {{1,0,0, 0,1,0, 0,0,1}, {0,0,0}};
#pragma unroll 2
    for (int k = 0; k < C1; k++) {
        int i = base + k;
        if (i < n) {
            float bl = __ldg(&inner[3*i+0]);
            float th = __ldg(&inner[3*i+1]);
            float ph = __ldg(&inner[3*i+2]);
            chain_step(bl, th, ph, s);
        }
    }
    aff_store(&sh[j*12], s);
    __syncthreads();
#pragma unroll
    for (int off = 1; off < TPB; off <<= 1) {
        Aff prev;
        bool has = (j >= off);
        if (has) prev = aff_load(&sh[(j-off)*12]);
        __syncthreads();
        if (has) {
            Aff cur = aff_load(&sh[j*12]);
            cur = cmb(prev, cur);
            aff_store(&sh[j*12], cur);
        }
        __syncthreads();
    }
    Aff r = aff_load(&sh[j*12]);
    aff_store(&g_chunkScan[chunk*12], r);
    if (j == TPB - 1) aff_store(&g_blockComp[b*12], r);
}

// ---------------------------------------------------------------------------
// K2: scan block composites, seed with frame of mainchain[:3], write bases.
// Also writes out[0..8] = mainchain frame0.
// ---------------------------------------------------------------------------
__global__ void __launch_bounds__(1024) k2_scan(int nb, const float* __restrict__ mc,
                                                float* __restrict__ out) {
    __shared__ float sh[MAXBLK * 12];
    __shared__ float s0sh[12];
    int j = threadIdx.x;
    if (j == 0) {
        float Ax = mc[0], Ay = mc[1], Az = mc[2];
        float Bx = mc[3], By = mc[4], Bz = mc[5];
        float Cx = mc[6], Cy = mc[7], Cz = mc[8];
        float bx = Cx-Bx, by = Cy-By, bz = Cz-Bz;
        float inv = rsqrtf(bx*bx + by*by + bz*bz);
        bx *= inv; by *= inv; bz *= inv;
        float ux = Bx-Ax, uy = By-Ay, uz = Bz-Az;
        float nx = uy*bz - uz*by, ny = uz*bx - ux*bz, nz = ux*by - uy*bx;
        inv = rsqrtf(nx*nx + ny*ny + nz*nz);
        nx *= inv; ny *= inv; nz *= inv;
        float rx = ny*bz - nz*by, ry = nz*bx - nx*bz, rz = nx*by - ny*bx;
        s0sh[0]=bx; s0sh[1]=by; s0sh[2]=bz;
        s0sh[3]=rx; s0sh[4]=ry; s0sh[5]=rz;
        s0sh[6]=nx; s0sh[7]=ny; s0sh[8]=nz;
        s0sh[9]=Cx; s0sh[10]=Cy; s0sh[11]=Cz;
    }
    if (j < 9) out[j] = mc[j];                    // frame0 rows
    if (j < nb) {
        Aff a = aff_load(&g_blockComp[j*12]);
        aff_store(&sh[j*12], a);
    }
    __syncthreads();
    for (int off = 1; off < nb; off <<= 1) {
        Aff prev;
        bool has = (j >= off) && (j < nb);
        if (has) prev = aff_load(&sh[(j-off)*12]);
        __syncthreads();
        if (has) {
            Aff cur = aff_load(&sh[j*12]);
            cur = cmb(prev, cur);
            aff_store(&sh[j*12], cur);
        }
        __syncthreads();
    }
    if (j < nb) {
        Aff s0 = aff_load(s0sh);
        Aff bp = (j == 0) ? s0 : cmb(s0, aff_load(&sh[(j-1)*12]));
        reortho(bp);
        aff_store(&g_basePrefix[j*12], bp);
    }
}

// ---------------------------------------------------------------------------
// K3: seed each chunk from its prefix, re-walk 50 atoms, write coordinates.
// ---------------------------------------------------------------------------
__global__ void __launch_bounds__(TPB) k3_emit(const float* __restrict__ inner, int n,
                                               float* __restrict__ out) {
    int j = threadIdx.x, b = blockIdx.x;
    int chunk = b * TPB + j;
    Aff s = aff_load(&g_basePrefix[b*12]);
    if (j > 0) {
        Aff pre = aff_load(&g_chunkScan[(chunk-1)*12]);
        s = cmb(s, pre);
    }
    reortho(s);
    int base = chunk * C1;
#pragma unroll 2
    for (int k = 0; k < C1; k++) {
        int i = base + k;
        if (i < n) {
            float bl = __ldg(&inner[3*i+0]);
            float th = __ldg(&inner[3*i+1]);
            float ph = __ldg(&inner[3*i+2]);
            chain_step(bl, th, ph, s);
            out[9 + 3*i + 0] = s.t[0];
            out[9 + 3*i + 1] = s.t[1];
            out[9 + 3*i + 2] = s.t[2];
        }
    }
}

extern "C" void kernel_launch(void* const* d_in, const int* in_sizes, int n_in,
                              void* d_out, int out_size) {
    const float* inner = (const float*)d_in[0];
    const float* mc    = (const float*)d_in[2];   // mainchain_coord_tensor (9 floats)
    float* out = (float*)d_out;
    int n = in_sizes[0] / 3;                      // number of atoms (3,000,000)
    int nchunks = (n + C1 - 1) / C1;
    int nblocks = (nchunks + TPB - 1) / TPB;      // 625 for n=3M (fits MAXBLK)

    k1_chunks<<<nblocks, TPB>>>(inner, n);
    k2_scan<<<1, 1024>>>(nblocks, mc, out);
    k3_emit<<<nblocks, TPB>>>(inner, n, out);
}

// round 3
// speedup vs baseline: 1.1086x; 1.1086x over previous
#include <cuda_runtime.h>
#include <cuda_bf16.h>
#include <cstdint>

// ============================================================================
// PNeRF coordinate extension as a chunked affine prefix scan (round 3).
// State (M, t): x_world = x_local @ M + t.  Step: M' = S M ; t' = t + bl*M'[0]
// Chunk composite (P, q): (M,t) -> (P M, q M + t).
// cmb(A earlier, B later) = (B.P A.P, B.q A.P + A.q)  -- associative.
// ============================================================================

#define C1   16      // atoms per chunk (per thread)
#define TPB  192     // chunks per block (6 warps)
#define NW   (TPB/32)
#define MAXCHUNKS 188160
#define MAXBLK    1024

struct Aff { float m[9]; float t[3]; };

__device__ float g_cs[12 * MAXCHUNKS];          // chunkScan, SoA: [comp][chunk]
__device__ float g_blockComp[MAXBLK * 12];
__device__ float g_basePrefix[MAXBLK * 12];

// ---------------------------------------------------------------------------
// Accurate fp32 sincos (immune to --use_fast_math): Cody-Waite + Cephes polys.
// ---------------------------------------------------------------------------
__device__ __forceinline__ void fsincos(float x, float& s, float& c) {
    float q = rintf(x * 0.6366197723675814f);
    float r = fmaf(q, -1.5707963705062866f, x);
    r = fmaf(q, 4.37113883e-8f, r);
    int iq = (int)q;
    float z = r * r;
    float ps = fmaf(z, -1.9515295891e-4f, 8.3321608736e-3f);
    ps = fmaf(z, ps, -1.6666654611e-1f);
    float sr = fmaf(r * z, ps, r);
    float pc = fmaf(z, 2.443315711809948e-5f, -1.388731625493765e-3f);
    pc = fmaf(z, pc, 4.166664568298827e-2f);
    float cr = fmaf(z * z, pc, fmaf(z, -0.5f, 1.0f));
    bool sw = (iq & 1);
    float ss = sw ? cr : sr;
    float cc = sw ? sr : cr;
    if (iq & 2)        ss = -ss;
    if ((iq + 1) & 2)  cc = -cc;
    s = ss; c = cc;
}

__device__ __forceinline__ Aff aff_identity() {
    Aff a = {{1,0,0, 0,1,0, 0,0,1}, {0,0,0}};
    return a;
}

// Combine: A earlier (or state), B later composite.
__device__ __forceinline__ Aff cmb(const Aff& A, const Aff& B) {
    Aff r;
#pragma unroll
    for (int i = 0; i < 3; i++) {
        float b0 = B.m[3*i], b1 = B.m[3*i+1], b2 = B.m[3*i+2];
#pragma unroll
        for (int j = 0; j < 3; j++)
            r.m[3*i+j] = fmaf(b0, A.m[j], fmaf(b1, A.m[3+j], b2 * A.m[6+j]));
    }
#pragma unroll
    for (int j = 0; j < 3; j++)
        r.t[j] = fmaf(B.t[0], A.m[j], fmaf(B.t[1], A.m[3+j],
                 fmaf(B.t[2], A.m[6+j], A.t[j])));
    return r;
}

__device__ __forceinline__ void chain_step(float bl, float th, float ph, Aff& s) {
    float st, ct, sp, cp;
    fsincos(th, st, ct);
    fsincos(ph, sp, cp);
    float a = cp * st, b = sp * st, c = cp * ct, d = sp * ct;
#pragma unroll
    for (int j = 0; j < 3; j++) {
        float m0 = s.m[j], m1 = s.m[3+j], m2 = s.m[6+j];
        float r0 = fmaf(ct, m0, fmaf(a, m1, b * m2));
        float r1 = fmaf(c,  m1, fmaf(d, m2, -st * m0));
        float r2 = fmaf(cp, m2, -sp * m1);
        s.m[j] = r0; s.m[3+j] = r1; s.m[6+j] = r2;
        s.t[j] = fmaf(bl, r0, s.t[j]);
    }
}

// First step from identity: s = S, t = bl*S[0].
__device__ __forceinline__ void first_step(float bl, float th, float ph, Aff& s) {
    float st, ct, sp, cp;
    fsincos(th, st, ct);
    fsincos(ph, sp, cp);
    s.m[0] = ct;        s.m[1] = cp*st;  s.m[2] = sp*st;
    s.m[3] = -st;       s.m[4] = cp*ct;  s.m[5] = sp*ct;
    s.m[6] = 0.0f;      s.m[7] = -sp;    s.m[8] = cp;
    s.t[0] = bl*s.m[0]; s.t[1] = bl*s.m[1]; s.t[2] = bl*s.m[2];
}

__device__ __forceinline__ void reortho(Aff& s) {
    float inv = rsqrtf(fmaf(s.m[0], s.m[0], fmaf(s.m[1], s.m[1], s.m[2]*s.m[2])));
    s.m[0] *= inv; s.m[1] *= inv; s.m[2] *= inv;
    float d = fmaf(s.m[6], s.m[0], fmaf(s.m[7], s.m[1], s.m[8]*s.m[2]));
    s.m[6] = fmaf(-d, s.m[0], s.m[6]);
    s.m[7] = fmaf(-d, s.m[1], s.m[7]);
    s.m[8] = fmaf(-d, s.m[2], s.m[8]);
    inv = rsqrtf(fmaf(s.m[6], s.m[6], fmaf(s.m[7], s.m[7], s.m[8]*s.m[8])));
    s.m[6] *= inv; s.m[7] *= inv; s.m[8] *= inv;
    s.m[3] = s.m[7]*s.m[2] - s.m[8]*s.m[1];
    s.m[4] = s.m[8]*s.m[0] - s.m[6]*s.m[2];
    s.m[5] = s.m[6]*s.m[1] - s.m[7]*s.m[0];
}

__device__ __forceinline__ void aff_store(float* p, const Aff& a) {
#pragma unroll
    for (int i = 0; i < 9; i++) p[i] = a.m[i];
#pragma unroll
    for (int i = 0; i < 3; i++) p[9+i] = a.t[i];
}
__device__ __forceinline__ Aff aff_load(const float* p) {
    Aff a;
#pragma unroll
    for (int i = 0; i < 9; i++) a.m[i] = p[i];
#pragma unroll
    for (int i = 0; i < 3; i++) a.t[i] = p[9+i];
    return a;
}

__device__ __forceinline__ Aff aff_shfl_up(const Aff& a, int delta) {
    Aff r;
#pragma unroll
    for (int i = 0; i < 9; i++) r.m[i] = __shfl_up_sync(0xffffffffu, a.m[i], delta);
#pragma unroll
    for (int i = 0; i < 3; i++) r.t[i] = __shfl_up_sync(0xffffffffu, a.t[i], delta);
    return r;
}

// ---------------------------------------------------------------------------
// K1: per-chunk composites + block scan (warp shuffle) + block composite.
// ---------------------------------------------------------------------------
__global__ void __launch_bounds__(TPB) k1_chunks(const float* __restrict__ inner,
                                                 int n, int nchunks) {
    __shared__ float swc[NW * 12];
    int tid = threadIdx.x, b = blockIdx.x;
    int lane = tid & 31, wid = tid >> 5;
    int chunk = b * TPB + tid;
    int base = chunk * C1;

    Aff s = aff_identity();
    if (chunk < nchunks) {
        {
            float bl = __ldg(&inner[3*base+0]);
            float th = __ldg(&inner[3*base+1]);
            float ph = __ldg(&inner[3*base+2]);
            first_step(bl, th, ph, s);
        }
#pragma unroll
        for (int k = 1; k < C1; k++) {
            int i = base + k;
            if (i < n) {
                float bl = __ldg(&inner[3*i+0]);
                float th = __ldg(&inner[3*i+1]);
                float ph = __ldg(&inner[3*i+2]);
                chain_step(bl, th, ph, s);
            }
        }
    }
    // warp-level inclusive scan
#pragma unroll
    for (int off = 1; off < 32; off <<= 1) {
        Aff p = aff_shfl_up(s, off);
        if (lane >= off) s = cmb(p, s);
    }
    if (lane == 31) aff_store(&swc[wid*12], s);
    __syncthreads();
    // warp 0 scans the NW warp composites
    if (wid == 0) {
        Aff w = (lane < NW) ? aff_load(&swc[lane*12]) : aff_identity();
#pragma unroll
        for (int off = 1; off < NW; off <<= 1) {
            Aff p = aff_shfl_up(w, off);
            if (lane >= off) w = cmb(p, w);
        }
        if (lane < NW) aff_store(&swc[lane*12], w);
    }
    __syncthreads();
    if (wid > 0) {
        Aff p = aff_load(&swc[(wid-1)*12]);
        s = cmb(p, s);
    }
    // SoA coalesced store of inclusive chunk scans
    if (chunk < nchunks) {
#pragma unroll
        for (int c = 0; c < 9; c++)  g_cs[c*MAXCHUNKS + chunk] = s.m[c];
#pragma unroll
        for (int c = 0; c < 3; c++)  g_cs[(9+c)*MAXCHUNKS + chunk] = s.t[c];
    }
    if (tid == TPB - 1) aff_store(&g_blockComp[b*12], s);
}

// ---------------------------------------------------------------------------
// K2: scan block composites (hierarchical shuffle), seed with mainchain frame.
// Exclusive prefix obtained from the inclusive shuffle scan itself (no 48KB
// smem staging buffer): e = shfl_up(inclusive,1); lane0 takes scanned warp
// total of the previous warp; tid 0 takes identity.
// ---------------------------------------------------------------------------
__global__ void __launch_bounds__(1024) k2_scan(int nb, const float* __restrict__ mc,
                                                float* __restrict__ out) {
    __shared__ float swc[32 * 12];
    __shared__ float s0sh[12];
    int tid = threadIdx.x, lane = tid & 31, wid = tid >> 5;
    if (tid == 0) {
        float Ax = mc[0], Ay = mc[1], Az = mc[2];
        float Bx = mc[3], By = mc[4], Bz = mc[5];
        float Cx = mc[6], Cy = mc[7], Cz = mc[8];
        float bx = Cx-Bx, by = Cy-By, bz = Cz-Bz;
        float inv = rsqrtf(bx*bx + by*by + bz*bz);
        bx *= inv; by *= inv; bz *= inv;
        float ux = Bx-Ax, uy = By-Ay, uz = Bz-Az;
        float nx = uy*bz - uz*by, ny = uz*bx - ux*bz, nz = ux*by - uy*bx;
        inv = rsqrtf(nx*nx + ny*ny + nz*nz);
        nx *= inv; ny *= inv; nz *= inv;
        s0sh[0]=bx; s0sh[1]=by; s0sh[2]=bz;
        s0sh[3]=ny*bz - nz*by; s0sh[4]=nz*bx - nx*bz; s0sh[5]=nx*by - ny*bx;
        s0sh[6]=nx; s0sh[7]=ny; s0sh[8]=nz;
        s0sh[9]=Cx; s0sh[10]=Cy; s0sh[11]=Cz;
    }
    if (tid < 9) out[tid] = mc[tid];
    Aff s = (tid < nb) ? aff_load(&g_blockComp[tid*12]) : aff_identity();
#pragma unroll
    for (int off = 1; off < 32; off <<= 1) {
        Aff p = aff_shfl_up(s, off);
        if (lane >= off) s = cmb(p, s);
    }
    if (lane == 31) aff_store(&swc[wid*12], s);
    __syncthreads();
    if (wid == 0) {
        Aff w = aff_load(&swc[lane*12]);   // 32 warps always present
#pragma unroll
        for (int off = 1; off < 32; off <<= 1) {
            Aff p = aff_shfl_up(w, off);
            if (lane >= off) w = cmb(p, w);
        }
        aff_store(&swc[lane*12], w);
    }
    __syncthreads();
    if (wid > 0) s = cmb(aff_load(&swc[(wid-1)*12]), s);  // full inclusive
    // exclusive prefix e = inclusive of tid-1
    Aff e = aff_shfl_up(s, 1);
    if (lane == 0 && wid > 0) e = aff_load(&swc[(wid-1)*12]);
    if (tid < nb) {
        Aff s0 = aff_load(s0sh);
        Aff bp = (tid == 0) ? s0 : cmb(s0, e);
        reortho(bp);
        aff_store(&g_basePrefix[tid*12], bp);
    }
}

// ---------------------------------------------------------------------------
// K3: seed from prefix, re-walk C1 atoms, stage coords in smem, flush coalesced.
// ---------------------------------------------------------------------------
#define OROW 49   // padded floats per thread row (odd -> conflict-free)
__global__ void __launch_bounds__(TPB) k3_emit(const float* __restrict__ inner,
                                               int n, int nchunks,
                                               float* __restrict__ out) {
    __shared__ float sout[TPB * OROW];   // 192*49*4 = 37632 B
    int tid = threadIdx.x, b = blockIdx.x;
    int chunk = b * TPB + tid;

    if (chunk < nchunks) {
        Aff s = aff_load(&g_basePrefix[b*12]);
        if (tid > 0) {
            Aff pre;
#pragma unroll
            for (int c = 0; c < 9; c++) pre.m[c] = g_cs[c*MAXCHUNKS + chunk - 1];
#pragma unroll
            for (int c = 0; c < 3; c++) pre.t[c] = g_cs[(9+c)*MAXCHUNKS + chunk - 1];
            s = cmb(s, pre);
        }
        reortho(s);
        int base = chunk * C1;
        float* row = &sout[tid * OROW];
#pragma unroll
        for (int k = 0; k < C1; k++) {
            int i = base + k;
            if (i < n) {
                float bl = __ldg(&inner[3*i+0]);
                float th = __ldg(&inner[3*i+1]);
                float ph = __ldg(&inner[3*i+2]);
                chain_step(bl, th, ph, s);
                row[3*k+0] = s.t[0];
                row[3*k+1] = s.t[1];
                row[3*k+2] = s.t[2];
            }
        }
    }
    __syncthreads();
    // coalesced flush: global float index f within block tile -> smem[f/48*OROW + f%48]
    long long tile0 = (long long)b * TPB * C1 * 3;
    int totalF = (int)min((long long)(TPB * C1 * 3), (long long)n * 3 - tile0);
    float* gout = out + 9 + tile0;
#pragma unroll 4
    for (int f = tid; f < totalF; f += TPB) {
        int jj = f / (C1*3);
        int kk = f - jj * (C1*3);
        gout[f] = sout[jj * OROW + kk];
    }
}

extern "C" void kernel_launch(void* const* d_in, const int* in_sizes, int n_in,
                              void* d_out, int out_size) {
    const float* inner = (const float*)d_in[0];
    const float* mc    = (const float*)d_in[2];
    float* out = (float*)d_out;
    int n = in_sizes[0] / 3;
    int nchunks = (n + C1 - 1) / C1;              // 187500
    int nblocks = (nchunks + TPB - 1) / TPB;      // 977  (<= 1024)

    k1_chunks<<<nblocks, TPB>>>(inner, n, nchunks);
    k2_scan<<<1, 1024>>>(nblocks, mc, out);
    k3_emit<<<nblocks, TPB>>>(inner, n, nchunks, out);
}

// round 4
// speedup vs baseline: 2.0862x; 1.8819x over previous
#include <cuda_runtime.h>
#include <cuda_bf16.h>
#include <cstdint>

// ============================================================================
// PNeRF coordinate extension as a chunked affine prefix scan (round 4).
// State (M, t): x_world = x_local @ M + t.  Step: M' = S M ; t' = t + bl*M'[0]
// Chunk composite (P, q): (M,t) -> (P M, q M + t). cmb is associative.
// Round 4: smem-staged transposed input tiles (conflict-free LDS walk),
//          in-place output staging in k3, coalesced global traffic only.
// ============================================================================

#define C1    16                 // atoms per chunk (per thread)
#define TPB   192                // chunks per block (6 warps)
#define NW    (TPB/32)
#define Q     (3*C1)             // 48 floats per chunk
#define PAD   193                // q-row stride (odd -> conflict-free walk LDS)
#define TILE_F (TPB*C1*3)        // 9216 floats per block tile
#define MAXCHUNKS 188160
#define MAXBLK    1024

struct Aff { float m[9]; float t[3]; };

__device__ float g_cs[12 * MAXCHUNKS];          // chunkScan, SoA: [comp][chunk]
__device__ float g_blockComp[MAXBLK * 12];
__device__ float g_basePrefix[MAXBLK * 12];

// ---------------------------------------------------------------------------
// Accurate fp32 sincos (immune to --use_fast_math): Cody-Waite + Cephes polys.
// ---------------------------------------------------------------------------
__device__ __forceinline__ void fsincos(float x, float& s, float& c) {
    float q = rintf(x * 0.6366197723675814f);
    float r = fmaf(q, -1.5707963705062866f, x);
    r = fmaf(q, 4.37113883e-8f, r);
    int iq = (int)q;
    float z = r * r;
    float ps = fmaf(z, -1.9515295891e-4f, 8.3321608736e-3f);
    ps = fmaf(z, ps, -1.6666654611e-1f);
    float sr = fmaf(r * z, ps, r);
    float pc = fmaf(z, 2.443315711809948e-5f, -1.388731625493765e-3f);
    pc = fmaf(z, pc, 4.166664568298827e-2f);
    float cr = fmaf(z * z, pc, fmaf(z, -0.5f, 1.0f));
    bool sw = (iq & 1);
    float ss = sw ? cr : sr;
    float cc = sw ? sr : cr;
    if (iq & 2)        ss = -ss;
    if ((iq + 1) & 2)  cc = -cc;
    s = ss; c = cc;
}

__device__ __forceinline__ Aff aff_identity() {
    Aff a = {{1,0,0, 0,1,0, 0,0,1}, {0,0,0}};
    return a;
}

// Combine: A earlier (or state), B later composite.
__device__ __forceinline__ Aff cmb(const Aff& A, const Aff& B) {
    Aff r;
#pragma unroll
    for (int i = 0; i < 3; i++) {
        float b0 = B.m[3*i], b1 = B.m[3*i+1], b2 = B.m[3*i+2];
#pragma unroll
        for (int j = 0; j < 3; j++)
            r.m[3*i+j] = fmaf(b0, A.m[j], fmaf(b1, A.m[3+j], b2 * A.m[6+j]));
    }
#pragma unroll
    for (int j = 0; j < 3; j++)
        r.t[j] = fmaf(B.t[0], A.m[j], fmaf(B.t[1], A.m[3+j],
                 fmaf(B.t[2], A.m[6+j], A.t[j])));
    return r;
}

__device__ __forceinline__ void chain_step(float bl, float th, float ph, Aff& s) {
    float st, ct, sp, cp;
    fsincos(th, st, ct);
    fsincos(ph, sp, cp);
    float a = cp * st, b = sp * st, c = cp * ct, d = sp * ct;
#pragma unroll
    for (int j = 0; j < 3; j++) {
        float m0 = s.m[j], m1 = s.m[3+j], m2 = s.m[6+j];
        float r0 = fmaf(ct, m0, fmaf(a, m1, b * m2));
        float r1 = fmaf(c,  m1, fmaf(d, m2, -st * m0));
        float r2 = fmaf(cp, m2, -sp * m1);
        s.m[j] = r0; s.m[3+j] = r1; s.m[6+j] = r2;
        s.t[j] = fmaf(bl, r0, s.t[j]);
    }
}

// First step from identity: s = S, t = bl*S[0].
__device__ __forceinline__ void first_step(float bl, float th, float ph, Aff& s) {
    float st, ct, sp, cp;
    fsincos(th, st, ct);
    fsincos(ph, sp, cp);
    s.m[0] = ct;        s.m[1] = cp*st;  s.m[2] = sp*st;
    s.m[3] = -st;       s.m[4] = cp*ct;  s.m[5] = sp*ct;
    s.m[6] = 0.0f;      s.m[7] = -sp;    s.m[8] = cp;
    s.t[0] = bl*s.m[0]; s.t[1] = bl*s.m[1]; s.t[2] = bl*s.m[2];
}

__device__ __forceinline__ void reortho(Aff& s) {
    float inv = rsqrtf(fmaf(s.m[0], s.m[0], fmaf(s.m[1], s.m[1], s.m[2]*s.m[2])));
    s.m[0] *= inv; s.m[1] *= inv; s.m[2] *= inv;
    float d = fmaf(s.m[6], s.m[0], fmaf(s.m[7], s.m[1], s.m[8]*s.m[2]));
    s.m[6] = fmaf(-d, s.m[0], s.m[6]);
    s.m[7] = fmaf(-d, s.m[1], s.m[7]);
    s.m[8] = fmaf(-d, s.m[2], s.m[8]);
    inv = rsqrtf(fmaf(s.m[6], s.m[6], fmaf(s.m[7], s.m[7], s.m[8]*s.m[8])));
    s.m[6] *= inv; s.m[7] *= inv; s.m[8] *= inv;
    s.m[3] = s.m[7]*s.m[2] - s.m[8]*s.m[1];
    s.m[4] = s.m[8]*s.m[0] - s.m[6]*s.m[2];
    s.m[5] = s.m[6]*s.m[1] - s.m[7]*s.m[0];
}

__device__ __forceinline__ void aff_store(float* p, const Aff& a) {
#pragma unroll
    for (int i = 0; i < 9; i++) p[i] = a.m[i];
#pragma unroll
    for (int i = 0; i < 3; i++) p[9+i] = a.t[i];
}
__device__ __forceinline__ Aff aff_load(const float* p) {
    Aff a;
#pragma unroll
    for (int i = 0; i < 9; i++) a.m[i] = p[i];
#pragma unroll
    for (int i = 0; i < 3; i++) a.t[i] = p[9+i];
    return a;
}

__device__ __forceinline__ Aff aff_shfl_up(const Aff& a, int delta) {
    Aff r;
#pragma unroll
    for (int i = 0; i < 9; i++) r.m[i] = __shfl_up_sync(0xffffffffu, a.m[i], delta);
#pragma unroll
    for (int i = 0; i < 3; i++) r.t[i] = __shfl_up_sync(0xffffffffu, a.t[i], delta);
    return r;
}

// Stage a block tile (nfl floats at gin) into transposed smem layout
// st[q*PAD + j], q = f%Q, j = f/Q.  Fast path: full tile via float4.
__device__ __forceinline__ void stage_in(float* st, const float* __restrict__ gin,
                                          int nfl, int tid) {
    if (nfl == TILE_F) {
        const float4* g4 = (const float4*)gin;
        int q0 = (4*tid) % Q;            // invariant across iterations
        int j0 = (4*tid) / Q;
#pragma unroll
        for (int it = 0; it < TILE_F/4/TPB; it++) {     // 12
            float4 v = g4[tid + it*TPB];
            float* p = &st[q0*PAD + j0 + 16*it];
            p[0]     = v.x;
            p[PAD]   = v.y;
            p[2*PAD] = v.z;
            p[3*PAD] = v.w;
        }
    } else {
        int q0 = tid % Q, j0 = tid / Q;
        for (int f = tid; f < nfl; f += TPB) {
            st[q0*PAD + j0] = gin[f];
            j0 += TPB/Q;                  // 4
        }
    }
}

// ---------------------------------------------------------------------------
// K1: stage tile, per-chunk composites, block scan (shuffle), store SoA scans.
// ---------------------------------------------------------------------------
__global__ void __launch_bounds__(TPB) k1_chunks(const float* __restrict__ inner,
                                                 int n, int nchunks) {
    __shared__ float st[Q * PAD];       // 9264 floats = 37056 B
    __shared__ float swc[NW * 12];
    int tid = threadIdx.x, b = blockIdx.x;
    int lane = tid & 31, wid = tid >> 5;
    int chunk = b * TPB + tid;

    long long tile0 = (long long)b * TILE_F;
    int nfl = (int)min((long long)TILE_F, (long long)n * 3 - tile0);
    stage_in(st, inner + tile0, nfl, tid);
    __syncthreads();

    Aff s = aff_identity();
    if (chunk < nchunks) {
        int base = chunk * C1;
        const float* col = &st[tid];
        if (base + C1 <= n) {
            first_step(col[0], col[PAD], col[2*PAD], s);
#pragma unroll
            for (int k = 1; k < C1; k++)
                chain_step(col[(3*k)*PAD], col[(3*k+1)*PAD], col[(3*k+2)*PAD], s);
        } else {
            int lim = n - base;
            if (lim > 0) first_step(col[0], col[PAD], col[2*PAD], s);
            for (int k = 1; k < lim; k++)
                chain_step(col[(3*k)*PAD], col[(3*k+1)*PAD], col[(3*k+2)*PAD], s);
        }
    }
    // warp-level inclusive scan
#pragma unroll
    for (int off = 1; off < 32; off <<= 1) {
        Aff p = aff_shfl_up(s, off);
        if (lane >= off) s = cmb(p, s);
    }
    if (lane == 31) aff_store(&swc[wid*12], s);
    __syncthreads();
    if (wid == 0) {
        Aff w = (lane < NW) ? aff_load(&swc[lane*12]) : aff_identity();
#pragma unroll
        for (int off = 1; off < NW; off <<= 1) {
            Aff p = aff_shfl_up(w, off);
            if (lane >= off) w = cmb(p, w);
        }
        if (lane < NW) aff_store(&swc[lane*12], w);
    }
    __syncthreads();
    if (wid > 0) s = cmb(aff_load(&swc[(wid-1)*12]), s);

    if (chunk < nchunks) {
#pragma unroll
        for (int c = 0; c < 9; c++)  g_cs[c*MAXCHUNKS + chunk] = s.m[c];
#pragma unroll
        for (int c = 0; c < 3; c++)  g_cs[(9+c)*MAXCHUNKS + chunk] = s.t[c];
    }
    if (tid == TPB - 1) aff_store(&g_blockComp[b*12], s);
}

// ---------------------------------------------------------------------------
// K2: scan block composites (hierarchical shuffle), seed with mainchain frame.
// ---------------------------------------------------------------------------
__global__ void __launch_bounds__(1024) k2_scan(int nb, const float* __restrict__ mc,
                                                float* __restrict__ out) {
    __shared__ float swc[32 * 12];
    __shared__ float s0sh[12];
    int tid = threadIdx.x, lane = tid & 31, wid = tid >> 5;
    if (tid == 0) {
        float Ax = mc[0], Ay = mc[1], Az = mc[2];
        float Bx = mc[3], By = mc[4], Bz = mc[5];
        float Cx = mc[6], Cy = mc[7], Cz = mc[8];
        float bx = Cx-Bx, by = Cy-By, bz = Cz-Bz;
        float inv = rsqrtf(bx*bx + by*by + bz*bz);
        bx *= inv; by *= inv; bz *= inv;
        float ux = Bx-Ax, uy = By-Ay, uz = Bz-Az;
        float nx = uy*bz - uz*by, ny = uz*bx - ux*bz, nz = ux*by - uy*bx;
        inv = rsqrtf(nx*nx + ny*ny + nz*nz);
        nx *= inv; ny *= inv; nz *= inv;
        s0sh[0]=bx; s0sh[1]=by; s0sh[2]=bz;
        s0sh[3]=ny*bz - nz*by; s0sh[4]=nz*bx - nx*bz; s0sh[5]=nx*by - ny*bx;
        s0sh[6]=nx; s0sh[7]=ny; s0sh[8]=nz;
        s0sh[9]=Cx; s0sh[10]=Cy; s0sh[11]=Cz;
    }
    if (tid < 9) out[tid] = mc[tid];
    Aff s = (tid < nb) ? aff_load(&g_blockComp[tid*12]) : aff_identity();
#pragma unroll
    for (int off = 1; off < 32; off <<= 1) {
        Aff p = aff_shfl_up(s, off);
        if (lane >= off) s = cmb(p, s);
    }
    if (lane == 31) aff_store(&swc[wid*12], s);
    __syncthreads();
    if (wid == 0) {
        Aff w = aff_load(&swc[lane*12]);
#pragma unroll
        for (int off = 1; off < 32; off <<= 1) {
            Aff p = aff_shfl_up(w, off);
            if (lane >= off) w = cmb(p, w);
        }
        aff_store(&swc[lane*12], w);
    }
    __syncthreads();
    if (wid > 0) s = cmb(aff_load(&swc[(wid-1)*12]), s);  // full inclusive
    Aff e = aff_shfl_up(s, 1);                             // exclusive prefix
    if (lane == 0 && wid > 0) e = aff_load(&swc[(wid-1)*12]);
    if (tid < nb) {
        Aff s0 = aff_load(s0sh);
        Aff bp = (tid == 0) ? s0 : cmb(s0, e);
        reortho(bp);
        aff_store(&g_basePrefix[tid*12], bp);
    }
}

// ---------------------------------------------------------------------------
// K3: stage input, seed from prefix, walk (overwriting input cells with
// coordinates in place), flush coalesced.
// ---------------------------------------------------------------------------
__global__ void __launch_bounds__(TPB) k3_emit(const float* __restrict__ inner,
                                               int n, int nchunks,
                                               float* __restrict__ out) {
    __shared__ float st[Q * PAD];
    int tid = threadIdx.x, b = blockIdx.x;
    int chunk = b * TPB + tid;

    long long tile0 = (long long)b * TILE_F;
    int nfl = (int)min((long long)TILE_F, (long long)n * 3 - tile0);
    stage_in(st, inner + tile0, nfl, tid);
    __syncthreads();

    if (chunk < nchunks) {
        Aff s = aff_load(&g_basePrefix[b*12]);
        if (tid > 0) {
            Aff pre;
#pragma unroll
            for (int c = 0; c < 9; c++) pre.m[c] = g_cs[c*MAXCHUNKS + chunk - 1];
#pragma unroll
            for (int c = 0; c < 3; c++) pre.t[c] = g_cs[(9+c)*MAXCHUNKS + chunk - 1];
            s = cmb(s, pre);
        }
        reortho(s);
        int base = chunk * C1;
        float* col = &st[tid];
        int lim = (base + C1 <= n) ? C1 : (n - base);
        if (lim == C1) {
#pragma unroll
            for (int k = 0; k < C1; k++) {
                chain_step(col[(3*k)*PAD], col[(3*k+1)*PAD], col[(3*k+2)*PAD], s);
                col[(3*k)*PAD]   = s.t[0];
                col[(3*k+1)*PAD] = s.t[1];
                col[(3*k+2)*PAD] = s.t[2];
            }
        } else {
            for (int k = 0; k < lim; k++) {
                chain_step(col[(3*k)*PAD], col[(3*k+1)*PAD], col[(3*k+2)*PAD], s);
                col[(3*k)*PAD]   = s.t[0];
                col[(3*k+1)*PAD] = s.t[1];
                col[(3*k+2)*PAD] = s.t[2];
            }
        }
    }
    __syncthreads();
    // coalesced scalar flush (out+9 is only 4B-aligned, so no STG.128)
    float* gout = out + 9 + tile0;
    int q0 = tid % Q, j0 = tid / Q;
    for (int f = tid; f < nfl; f += TPB) {
        gout[f] = st[q0*PAD + j0];
        j0 += TPB/Q;
    }
}

extern "C" void kernel_launch(void* const* d_in, const int* in_sizes, int n_in,
                              void* d_out, int out_size) {
    const float* inner = (const float*)d_in[0];
    const float* mc    = (const float*)d_in[2];
    float* out = (float*)d_out;
    int n = in_sizes[0] / 3;
    int nchunks = (n + C1 - 1) / C1;              // 187500
    int nblocks = (nchunks + TPB - 1) / TPB;      // 977  (<= 1024)

    k1_chunks<<<nblocks, TPB>>>(inner, n, nchunks);
    k2_scan<<<1, 1024>>>(nblocks, mc, out);
    k3_emit<<<nblocks, TPB>>>(inner, n, nchunks, out);
}

// round 6
// speedup vs baseline: 2.1981x; 1.0536x over previous
#include <cuda_runtime.h>
#include <cuda_bf16.h>
#include <cstdint>

// ============================================================================
// PNeRF coordinate extension as a chunked affine prefix scan (round 5 resubmit).
// State (M, t): x_world = x_local @ M + t.  Step: M' = S M ; t' = t + bl*M'[0]
// Round 5: linear padded smem rows (conflict-free LDS.128/STS.128),
//          theta-specialized sincos (bond_angle in [1.9,2.1] -> quadrant 1),
//          vectorized k3 in-place write-back.
// ============================================================================

#define C1    16                 // atoms per chunk (per thread)
#define TPB   192                // chunks per block (6 warps)
#define NW    (TPB/32)
#define Q     (3*C1)             // 48 floats per chunk
#define ROWF  52                 // padded floats per row (208B, 16B-aligned, conflict-free .128)
#define ROW4  13                 // float4 per row
#define TILE_F (TPB*C1*3)        // 9216 floats per block tile
#define MAXCHUNKS 188160
#define MAXBLK    1024

struct Aff { float m[9]; float t[3]; };

__device__ float g_cs[12 * MAXCHUNKS];          // chunkScan, SoA: [comp][chunk]
__device__ float g_blockComp[MAXBLK * 12];
__device__ float g_basePrefix[MAXBLK * 12];

// ---------------------------------------------------------------------------
// Accurate fp32 sincos (immune to --use_fast_math): Cody-Waite + Cephes polys.
// General path for phi in [-pi, pi].
// ---------------------------------------------------------------------------
__device__ __forceinline__ void fsincos(float x, float& s, float& c) {
    float q = rintf(x * 0.6366197723675814f);
    float r = fmaf(q, -1.5707963705062866f, x);
    r = fmaf(q, 4.37113883e-8f, r);
    int iq = (int)q;
    float z = r * r;
    float ps = fmaf(z, -1.9515295891e-4f, 8.3321608736e-3f);
    ps = fmaf(z, ps, -1.6666654611e-1f);
    float sr = fmaf(r * z, ps, r);
    float pc = fmaf(z, 2.443315711809948e-5f, -1.388731625493765e-3f);
    pc = fmaf(z, pc, 4.166664568298827e-2f);
    float cr = fmaf(z * z, pc, fmaf(z, -0.5f, 1.0f));
    bool sw = (iq & 1);
    float ss = sw ? cr : sr;
    float cc = sw ? sr : cr;
    if (iq & 2)        ss = -ss;
    if ((iq + 1) & 2)  cc = -cc;
    s = ss; c = cc;
}

// Theta path: bond_angle in [1.9, 2.1] -> quadrant q == 1 always.
// Bit-identical to the general path with q=1: sin(th)=cos r, cos(th)=-sin r.
__device__ __forceinline__ void fsincos_th(float x, float& s, float& c) {
    float r = (x - 1.5707963705062866f) + 4.37113883e-8f;
    float z = r * r;
    float ps = fmaf(z, -1.9515295891e-4f, 8.3321608736e-3f);
    ps = fmaf(z, ps, -1.6666654611e-1f);
    float sr = fmaf(r * z, ps, r);
    float pc = fmaf(z, 2.443315711809948e-5f, -1.388731625493765e-3f);
    pc = fmaf(z, pc, 4.166664568298827e-2f);
    float cr = fmaf(z * z, pc, fmaf(z, -0.5f, 1.0f));
    s = cr; c = -sr;
}

__device__ __forceinline__ Aff aff_identity() {
    Aff a = {{1,0,0, 0,1,0, 0,0,1}, {0,0,0}};
    return a;
}

// Combine: A earlier (or state), B later composite.
__device__ __forceinline__ Aff cmb(const Aff& A, const Aff& B) {
    Aff r;
#pragma unroll
    for (int i = 0; i < 3; i++) {
        float b0 = B.m[3*i], b1 = B.m[3*i+1], b2 = B.m[3*i+2];
#pragma unroll
        for (int j = 0; j < 3; j++)
            r.m[3*i+j] = fmaf(b0, A.m[j], fmaf(b1, A.m[3+j], b2 * A.m[6+j]));
    }
#pragma unroll
    for (int j = 0; j < 3; j++)
        r.t[j] = fmaf(B.t[0], A.m[j], fmaf(B.t[1], A.m[3+j],
                 fmaf(B.t[2], A.m[6+j], A.t[j])));
    return r;
}

__device__ __forceinline__ void chain_step(float bl, float th, float ph, Aff& s) {
    float st, ct, sp, cp;
    fsincos_th(th, st, ct);
    fsincos(ph, sp, cp);
    float a = cp * st, b = sp * st, c = cp * ct, d = sp * ct;
#pragma unroll
    for (int j = 0; j < 3; j++) {
        float m0 = s.m[j], m1 = s.m[3+j], m2 = s.m[6+j];
        float r0 = fmaf(ct, m0, fmaf(a, m1, b * m2));
        float r1 = fmaf(c,  m1, fmaf(d, m2, -st * m0));
        float r2 = fmaf(cp, m2, -sp * m1);
        s.m[j] = r0; s.m[3+j] = r1; s.m[6+j] = r2;
        s.t[j] = fmaf(bl, r0, s.t[j]);
    }
}

// First step from identity: s = S, t = bl*S[0].
__device__ __forceinline__ void first_step(float bl, float th, float ph, Aff& s) {
    float st, ct, sp, cp;
    fsincos_th(th, st, ct);
    fsincos(ph, sp, cp);
    s.m[0] = ct;        s.m[1] = cp*st;  s.m[2] = sp*st;
    s.m[3] = -st;       s.m[4] = cp*ct;  s.m[5] = sp*ct;
    s.m[6] = 0.0f;      s.m[7] = -sp;    s.m[8] = cp;
    s.t[0] = bl*s.m[0]; s.t[1] = bl*s.m[1]; s.t[2] = bl*s.m[2];
}

__device__ __forceinline__ void reortho(Aff& s) {
    float inv = rsqrtf(fmaf(s.m[0], s.m[0], fmaf(s.m[1], s.m[1], s.m[2]*s.m[2])));
    s.m[0] *= inv; s.m[1] *= inv; s.m[2] *= inv;
    float d = fmaf(s.m[6], s.m[0], fmaf(s.m[7], s.m[1], s.m[8]*s.m[2]));
    s.m[6] = fmaf(-d, s.m[0], s.m[6]);
    s.m[7] = fmaf(-d, s.m[1], s.m[7]);
    s.m[8] = fmaf(-d, s.m[2], s.m[8]);
    inv = rsqrtf(fmaf(s.m[6], s.m[6], fmaf(s.m[7], s.m[7], s.m[8]*s.m[8])));
    s.m[6] *= inv; s.m[7] *= inv; s.m[8] *= inv;
    s.m[3] = s.m[7]*s.m[2] - s.m[8]*s.m[1];
    s.m[4] = s.m[8]*s.m[0] - s.m[6]*s.m[2];
    s.m[5] = s.m[6]*s.m[1] - s.m[7]*s.m[0];
}

__device__ __forceinline__ void aff_store(float* p, const Aff& a) {
#pragma unroll
    for (int i = 0; i < 9; i++) p[i] = a.m[i];
#pragma unroll
    for (int i = 0; i < 3; i++) p[9+i] = a.t[i];
}
__device__ __forceinline__ Aff aff_load(const float* p) {
    Aff a;
#pragma unroll
    for (int i = 0; i < 9; i++) a.m[i] = p[i];
#pragma unroll
    for (int i = 0; i < 3; i++) a.t[i] = p[9+i];
    return a;
}

__device__ __forceinline__ Aff aff_shfl_up(const Aff& a, int delta) {
    Aff r;
#pragma unroll
    for (int i = 0; i < 9; i++) r.m[i] = __shfl_up_sync(0xffffffffu, a.m[i], delta);
#pragma unroll
    for (int i = 0; i < 3; i++) r.t[i] = __shfl_up_sync(0xffffffffu, a.t[i], delta);
    return r;
}

// Stage a block tile into padded linear rows: st[(f/Q)*ROWF + f%Q].
// Full-tile fast path: float4 copy; j advances by exactly 16 per iteration
// (TPB/12 == 16), k invariant.
__device__ __forceinline__ void stage_in(float* st, const float* __restrict__ gin,
                                          int nfl, int tid) {
    if (nfl == TILE_F) {
        const float4* g4 = (const float4*)gin;
        float4* s4 = (float4*)st;
        int j0 = tid / 12, k0 = tid - 12 * (tid / 12);
        int dst = j0 * ROW4 + k0;
#pragma unroll
        for (int it = 0; it < TILE_F/4/TPB; it++) {     // 12
            s4[dst] = g4[tid + it*TPB];
            dst += 16 * ROW4;
        }
    } else {
        int q0 = tid % Q, j0 = tid / Q;
        for (int f = tid; f < nfl; f += TPB) {
            st[j0*ROWF + q0] = gin[f];
            j0 += TPB/Q;
        }
    }
}

// ---------------------------------------------------------------------------
// K1: stage tile, per-chunk composites (vector walk), block scan, SoA stores.
// ---------------------------------------------------------------------------
__global__ void __launch_bounds__(TPB) k1_chunks(const float* __restrict__ inner,
                                                 int n, int nchunks) {
    __shared__ float st[TPB * ROWF];    // 39936 B
    __shared__ float swc[NW * 12];
    int tid = threadIdx.x, b = blockIdx.x;
    int lane = tid & 31, wid = tid >> 5;
    int chunk = b * TPB + tid;

    long long tile0 = (long long)b * TILE_F;
    int nfl = (int)min((long long)TILE_F, (long long)n * 3 - tile0);
    stage_in(st, inner + tile0, nfl, tid);
    __syncthreads();

    Aff s = aff_identity();
    if (chunk < nchunks) {
        int base = chunk * C1;
        if (base + C1 <= n) {
            const float4* row4 = (const float4*)st + tid * ROW4;
            float4 va = row4[0], vb = row4[1], vc = row4[2];
            first_step(va.x, va.y, va.z, s);
            chain_step(va.w, vb.x, vb.y, s);
            chain_step(vb.z, vb.w, vc.x, s);
            chain_step(vc.y, vc.z, vc.w, s);
#pragma unroll
            for (int G = 1; G < 4; G++) {
                va = row4[3*G]; vb = row4[3*G+1]; vc = row4[3*G+2];
                chain_step(va.x, va.y, va.z, s);
                chain_step(va.w, vb.x, vb.y, s);
                chain_step(vb.z, vb.w, vc.x, s);
                chain_step(vc.y, vc.z, vc.w, s);
            }
        } else {
            int lim = n - base;
            const float* col = st + tid * ROWF;
            if (lim > 0) first_step(col[0], col[1], col[2], s);
            for (int k = 1; k < lim; k++)
                chain_step(col[3*k], col[3*k+1], col[3*k+2], s);
        }
    }
    // warp-level inclusive scan
#pragma unroll
    for (int off = 1; off < 32; off <<= 1) {
        Aff p = aff_shfl_up(s, off);
        if (lane >= off) s = cmb(p, s);
    }
    if (lane == 31) aff_store(&swc[wid*12], s);
    __syncthreads();
    if (wid == 0) {
        Aff w = (lane < NW) ? aff_load(&swc[lane*12]) : aff_identity();
#pragma unroll
        for (int off = 1; off < NW; off <<= 1) {
            Aff p = aff_shfl_up(w, off);
            if (lane >= off) w = cmb(p, w);
        }
        if (lane < NW) aff_store(&swc[lane*12], w);
    }
    __syncthreads();
    if (wid > 0) s = cmb(aff_load(&swc[(wid-1)*12]), s);

    if (chunk < nchunks) {
#pragma unroll
        for (int c = 0; c < 9; c++)  g_cs[c*MAXCHUNKS + chunk] = s.m[c];
#pragma unroll
        for (int c = 0; c < 3; c++)  g_cs[(9+c)*MAXCHUNKS + chunk] = s.t[c];
    }
    if (tid == TPB - 1) aff_store(&g_blockComp[b*12], s);
}

// ---------------------------------------------------------------------------
// K2: scan block composites (hierarchical shuffle), seed with mainchain frame.
// ---------------------------------------------------------------------------
__global__ void __launch_bounds__(1024) k2_scan(int nb, const float* __restrict__ mc,
                                                float* __restrict__ out) {
    __shared__ float swc[32 * 12];
    __shared__ float s0sh[12];
    int tid = threadIdx.x, lane = tid & 31, wid = tid >> 5;
    if (tid == 0) {
        float Ax = mc[0], Ay = mc[1], Az = mc[2];
        float Bx = mc[3], By = mc[4], Bz = mc[5];
        float Cx = mc[6], Cy = mc[7], Cz = mc[8];
        float bx = Cx-Bx, by = Cy-By, bz = Cz-Bz;
        float inv = rsqrtf(bx*bx + by*by + bz*bz);
        bx *= inv; by *= inv; bz *= inv;
        float ux = Bx-Ax, uy = By-Ay, uz = Bz-Az;
        float nx = uy*bz - uz*by, ny = uz*bx - ux*bz, nz = ux*by - uy*bx;
        inv = rsqrtf(nx*nx + ny*ny + nz*nz);
        nx *= inv; ny *= inv; nz *= inv;
        s0sh[0]=bx; s0sh[1]=by; s0sh[2]=bz;
        s0sh[3]=ny*bz - nz*by; s0sh[4]=nz*bx - nx*bz; s0sh[5]=nx*by - ny*bx;
        s0sh[6]=nx; s0sh[7]=ny; s0sh[8]=nz;
        s0sh[9]=Cx; s0sh[10]=Cy; s0sh[11]=Cz;
    }
    if (tid < 9) out[tid] = mc[tid];
    Aff s = (tid < nb) ? aff_load(&g_blockComp[tid*12]) : aff_identity();
#pragma unroll
    for (int off = 1; off < 32; off <<= 1) {
        Aff p = aff_shfl_up(s, off);
        if (lane >= off) s = cmb(p, s);
    }
    if (lane == 31) aff_store(&swc[wid*12], s);
    __syncthreads();
    if (wid == 0) {
        Aff w = aff_load(&swc[lane*12]);
#pragma unroll
        for (int off = 1; off < 32; off <<= 1) {
            Aff p = aff_shfl_up(w, off);
            if (lane >= off) w = cmb(p, w);
        }
        aff_store(&swc[lane*12], w);
    }
    __syncthreads();
    if (wid > 0) s = cmb(aff_load(&swc[(wid-1)*12]), s);  // full inclusive
    Aff e = aff_shfl_up(s, 1);                             // exclusive prefix
    if (lane == 0 && wid > 0) e = aff_load(&swc[(wid-1)*12]);
    if (tid < nb) {
        Aff s0 = aff_load(s0sh);
        Aff bp = (tid == 0) ? s0 : cmb(s0, e);
        reortho(bp);
        aff_store(&g_basePrefix[tid*12], bp);
    }
}

// ---------------------------------------------------------------------------
// K3: stage, seed from prefix, vector walk with in-place float4 write-back,
//     coalesced scalar flush (out+9 is only 4B-aligned).
// ---------------------------------------------------------------------------
__global__ void __launch_bounds__(TPB) k3_emit(const float* __restrict__ inner,
                                               int n, int nchunks,
                                               float* __restrict__ out) {
    __shared__ float st[TPB * ROWF];
    int tid = threadIdx.x, b = blockIdx.x;
    int chunk = b * TPB + tid;

    long long tile0 = (long long)b * TILE_F;
    int nfl = (int)min((long long)TILE_F, (long long)n * 3 - tile0);
    stage_in(st, inner + tile0, nfl, tid);
    __syncthreads();

    if (chunk < nchunks) {
        Aff s = aff_load(&g_basePrefix[b*12]);
        if (tid > 0) {
            Aff pre;
#pragma unroll
            for (int c = 0; c < 9; c++) pre.m[c] = g_cs[c*MAXCHUNKS + chunk - 1];
#pragma unroll
            for (int c = 0; c < 3; c++) pre.t[c] = g_cs[(9+c)*MAXCHUNKS + chunk - 1];
            s = cmb(s, pre);
        }
        reortho(s);
        int base = chunk * C1;
        if (base + C1 <= n) {
            float4* row4 = (float4*)st + tid * ROW4;
#pragma unroll
            for (int G = 0; G < 4; G++) {
                float4 va = row4[3*G], vb = row4[3*G+1], vc = row4[3*G+2];
                float4 oa, ob, oc;
                chain_step(va.x, va.y, va.z, s); oa.x=s.t[0]; oa.y=s.t[1]; oa.z=s.t[2];
                chain_step(va.w, vb.x, vb.y, s); oa.w=s.t[0]; ob.x=s.t[1]; ob.y=s.t[2];
                chain_step(vb.z, vb.w, vc.x, s); ob.z=s.t[0]; ob.w=s.t[1]; oc.x=s.t[2];
                chain_step(vc.y, vc.z, vc.w, s); oc.y=s.t[0]; oc.z=s.t[1]; oc.w=s.t[2];
                row4[3*G] = oa; row4[3*G+1] = ob; row4[3*G+2] = oc;
            }
        } else {
            int lim = n - base;
            float* col = st + tid * ROWF;
            for (int k = 0; k < lim; k++) {
                chain_step(col[3*k], col[3*k+1], col[3*k+2], s);
                col[3*k]   = s.t[0];
                col[3*k+1] = s.t[1];
                col[3*k+2] = s.t[2];
            }
        }
    }
    __syncthreads();
    // coalesced scalar flush; q invariant across iterations (TPB % Q == 0)
    float* gout = out + 9 + tile0;
    int q0 = tid % Q, j0 = tid / Q;
#pragma unroll 8
    for (int f = tid; f < nfl; f += TPB) {
        gout[f] = st[j0*ROWF + q0];
        j0 += TPB/Q;
    }
}

extern "C" void kernel_launch(void* const* d_in, const int* in_sizes, int n_in,
                              void* d_out, int out_size) {
    const float* inner = (const float*)d_in[0];
    const float* mc    = (const float*)d_in[2];
    float* out = (float*)d_out;
    int n = in_sizes[0] / 3;
    int nchunks = (n + C1 - 1) / C1;              // 187500
    int nblocks = (nchunks + TPB - 1) / TPB;      // 977  (<= 1024)

    k1_chunks<<<nblocks, TPB>>>(inner, n, nchunks);
    k2_scan<<<1, 1024>>>(nblocks, mc, out);
    k3_emit<<<nblocks, TPB>>>(inner, n, nchunks, out);
}